// round 10
// baseline (speedup 1.0000x reference)
#include <cuda_runtime.h>
#include <math.h>

// Problem shapes
#define HH   51          // hidden size
#define HP   52          // padded hidden (unit h=51 inert: zero weights)
#define GPT  208         // gate-interleaved weight row stride = HP*4 floats
#define K1   52          // layer-1 K (padded)
#define K2   104         // layer-2 K: rows [0..51]=h1, [52..103]=h2
#define SST  36          // state row stride (floats), 16B-aligned
#define NSEQ 16
#define NT   416         // 52 hidden x 8 seq-pairs -> 13 warps
#define NBLK 128
#define TSZ  2048
#define XCH  64          // I/O staging chunk (timesteps)

// shared layout (floats)
#define OFF_W1 0                        // [K1][HP][4] gate-interleaved
#define OFF_W2 (OFF_W1 + K1*GPT)        // [K2][HP][4]
#define OFF_S0 (OFF_W2 + K2*GPT)        // state buf0: [K2][SST], dup pairs (h,h) x16 seqs
#define OFF_S1 (OFF_S0 + K2*SST)        // state buf1
#define OFF_X  (OFF_S1 + K2*SST)        // [XCH][16]  (transposed: t-major)
#define OFF_Y  (OFF_X  + NSEQ*XCH)      // [XCH][16]
#define OFF_WL (OFF_Y  + NSEQ*XCH)      // [52]: [0..50]=W_lin, [51]=b_lin
#define SMEM_FLOATS (OFF_WL + 52)

typedef unsigned long long u64;

__device__ __forceinline__ u64 pack2(float a, float b) {
    u64 d; asm("mov.b64 %0,{%1,%2};" : "=l"(d) : "f"(a), "f"(b)); return d;
}
__device__ __forceinline__ void unpack2(u64 v, float &a, float &b) {
    asm("mov.b64 {%0,%1},%2;" : "=f"(a), "=f"(b) : "l"(v));
}
__device__ __forceinline__ u64 ffma2(u64 a, u64 b, u64 c) {
    u64 d; asm("fma.rn.f32x2 %0,%1,%2,%3;" : "=l"(d) : "l"(a), "l"(b), "l"(c)); return d;
}

__device__ __forceinline__ float fsig(float x) {
    float e = __expf(fminf(-x, 80.f));
    return __fdividef(1.f, 1.f + e);
}
__device__ __forceinline__ float ftanh_f(float x) {
    float ax = fabsf(x);
    float e  = __expf(-2.f * ax);
    float t  = __fdividef(1.f - e, 1.f + e);
    return x >= 0.f ? t : -t;
}
__device__ __forceinline__ float lstm_act(u64 aif, u64 ago, float &c) {
    float gi, gf, gg, go;
    unpack2(aif, gi, gf);
    unpack2(ago, gg, go);
    float cn = fsig(gf) * c + fsig(gi) * ftanh_f(gg);
    c = cn;
    return fsig(go) * ftanh_f(cn);
}

__global__ __launch_bounds__(NT, 1)
void lstm2_kernel(const float* __restrict__ in,
                  const float* __restrict__ W_ih1,
                  const float* __restrict__ W_hh1,
                  const float* __restrict__ b_ih1,
                  const float* __restrict__ b_hh1,
                  const float* __restrict__ W_ih2,
                  const float* __restrict__ W_hh2,
                  const float* __restrict__ b_ih2,
                  const float* __restrict__ b_hh2,
                  const float* __restrict__ W_lin,
                  const float* __restrict__ b_lin,
                  float* __restrict__ out)
{
    extern __shared__ float sm[];
    float* sW1 = sm + OFF_W1;
    float* sW2 = sm + OFF_W2;
    float* sX  = sm + OFF_X;
    float* sY  = sm + OFF_Y;
    float* sWl = sm + OFF_WL;

    const int tid  = threadIdx.x;
    const int seq0 = blockIdx.x * NSEQ;

    // ---- one-time shared init: gate-interleaved k-major weights ----
    for (int i = tid; i < K1*GPT; i += NT) {
        int k = i / GPT, r = i % GPT, hh = r >> 2, q = r & 3;
        sW1[i] = (k < HH && hh < HH) ? W_hh1[(q*HH + hh)*HH + k] : 0.f;
    }
    for (int i = tid; i < K2*GPT; i += NT) {
        int k = i / GPT, r = i % GPT, hh = r >> 2, q = r & 3;
        float v = 0.f;
        if (hh < HH) {
            if (k < HH)                    v = W_ih2[(q*HH + hh)*HH + k];        // input = h1
            else if (k >= HP && k < HP+HH) v = W_hh2[(q*HH + hh)*HH + (k - HP)]; // recurrent h2
        }
        sW2[i] = v;
    }
    for (int i = tid; i < 2*K2*SST; i += NT) sm[OFF_S0 + i] = 0.f;
    for (int i = tid; i < 52; i += NT)
        sWl[i] = (i < HH) ? W_lin[i] : b_lin[0];

    // ---- per-thread tile: hidden h (tid>>3), seq pair sg (tid&7) ----
    const int h   = tid >> 3;        // 0..51 (51 inert)
    const int sg  = tid & 7;         // 0..7 -> seqs {2sg, 2sg+1}
    const int h4  = h * 4;
    const int sg4 = sg * 4;          // float offset of 16B dup-pair block

    // per-thread constants (in registers all 2048 steps)
    u64 wi_if, wi_go, b1_if, b1_go, b2_if, b2_go;
    {
        const bool ok = (h < HH);
        float w0 = ok ? W_ih1[0*HH + h] : 0.f;
        float w1 = ok ? W_ih1[1*HH + h] : 0.f;
        float w2 = ok ? W_ih1[2*HH + h] : 0.f;
        float w3 = ok ? W_ih1[3*HH + h] : 0.f;
        wi_if = pack2(w0, w1); wi_go = pack2(w2, w3);
        float a0 = ok ? b_ih1[0*HH + h] + b_hh1[0*HH + h] : 0.f;
        float a1 = ok ? b_ih1[1*HH + h] + b_hh1[1*HH + h] : 0.f;
        float a2 = ok ? b_ih1[2*HH + h] + b_hh1[2*HH + h] : 0.f;
        float a3 = ok ? b_ih1[3*HH + h] + b_hh1[3*HH + h] : 0.f;
        b1_if = pack2(a0, a1); b1_go = pack2(a2, a3);
        float e0 = ok ? b_ih2[0*HH + h] + b_hh2[0*HH + h] : 0.f;
        float e1 = ok ? b_ih2[1*HH + h] + b_hh2[1*HH + h] : 0.f;
        float e2 = ok ? b_ih2[2*HH + h] + b_hh2[2*HH + h] : 0.f;
        float e3 = ok ? b_ih2[3*HH + h] + b_hh2[3*HH + h] : 0.f;
        b2_if = pack2(e0, e1); b2_go = pack2(e2, e3);
    }

    float c1[2] = {0.f, 0.f};
    float c2[2] = {0.f, 0.f};

    float* sR  = sm + OFF_S0;   // prior-step state
    float* sWb = sm + OFF_S1;   // this step's state

    for (int t = 0; t < TSZ; t++) {
        const int tin = t & (XCH - 1);
        if (tin == 0) {
            __syncthreads();                 // init done (t=0) / sY complete
            if (t) {
                const int tp = t - XCH;
                for (int i = tid; i < NSEQ*XCH; i += NT) {
                    int s = i >> 6, j = i & 63;
                    out[(size_t)(seq0 + s) * TSZ + tp + j] = sY[j*16 + s];
                }
            }
            for (int i = tid; i < NSEQ*XCH; i += NT) {
                int s = i >> 6, j = i & 63;
                sX[j*16 + s] = in[(size_t)(seq0 + s) * TSZ + t + j];
            }
            __syncthreads();
        }

        // ===== Layer 1: fused matvec + activation =====
        {
            const float2 xs = *(const float2*)(sX + tin*16 + sg*2);  // (x_s0, x_s1)
            u64 x0 = pack2(xs.x, xs.x), x1 = pack2(xs.y, xs.y);
            u64 aif0 = ffma2(wi_if, x0, b1_if);
            u64 ago0 = ffma2(wi_go, x0, b1_go);
            u64 aif1 = ffma2(wi_if, x1, b1_if);
            u64 ago1 = ffma2(wi_go, x1, b1_go);
            #pragma unroll 4
            for (int k = 0; k < K1; k++) {
                ulonglong2 w  = *(const ulonglong2*)(sW1 + k*GPT + h4);
                ulonglong2 hv = *(const ulonglong2*)(sR  + k*SST + sg4);
                aif0 = ffma2(w.x, hv.x, aif0); ago0 = ffma2(w.y, hv.x, ago0);
                aif1 = ffma2(w.x, hv.y, aif1); ago1 = ffma2(w.y, hv.y, ago1);
            }
            float h0 = lstm_act(aif0, ago0, c1[0]);
            float h1v = lstm_act(aif1, ago1, c1[1]);
            *(float4*)(sWb + h*SST + sg4) = make_float4(h0, h0, h1v, h1v);
        }
        __syncthreads();   // h1(t) visible

        // ===== Layer 2: K=104 over [h1(t) | h2(t-1)] =====
        {
            u64 aif0 = b2_if, ago0 = b2_go, aif1 = b2_if, ago1 = b2_go;
            #pragma unroll 4
            for (int k = 0; k < K1; k++) {                 // h1(t) from write buffer
                ulonglong2 w  = *(const ulonglong2*)(sW2 + k*GPT + h4);
                ulonglong2 hv = *(const ulonglong2*)(sWb + k*SST + sg4);
                aif0 = ffma2(w.x, hv.x, aif0); ago0 = ffma2(w.y, hv.x, ago0);
                aif1 = ffma2(w.x, hv.y, aif1); ago1 = ffma2(w.y, hv.y, ago1);
            }
            #pragma unroll 4
            for (int k = K1; k < K2; k++) {                // h2(t-1) from read buffer
                ulonglong2 w  = *(const ulonglong2*)(sW2 + k*GPT + h4);
                ulonglong2 hv = *(const ulonglong2*)(sR  + k*SST + sg4);
                aif0 = ffma2(w.x, hv.x, aif0); ago0 = ffma2(w.y, hv.x, ago0);
                aif1 = ffma2(w.x, hv.y, aif1); ago1 = ffma2(w.y, hv.y, ago1);
            }
            float h0 = lstm_act(aif0, ago0, c2[0]);
            float h1v = lstm_act(aif1, ago1, c2[1]);
            *(float4*)(sWb + (HP + h)*SST + sg4) = make_float4(h0, h0, h1v, h1v);
        }
        __syncthreads();   // h2(t) visible

        // ===== output: y = h2 . W_lin + b_lin (warps 0-1, overlaps next layer-1) =====
        if (tid < 64) {
            int s = tid >> 2, pq = tid & 3;
            float acc = 0.f;
            #pragma unroll
            for (int k = pq; k < HH; k += 4)
                acc += sWb[(HP + k)*SST + s*2] * sWl[k];
            acc += __shfl_xor_sync(0xffffffffu, acc, 1);
            acc += __shfl_xor_sync(0xffffffffu, acc, 2);
            if (pq == 0) sY[tin*16 + s] = acc + sWl[HH];
        }

        { float* tp_ = sR; sR = sWb; sWb = tp_; }
    }

    __syncthreads();
    {
        const int tp = TSZ - XCH;
        for (int i = tid; i < NSEQ*XCH; i += NT) {
            int s = i >> 6, j = i & 63;
            out[(size_t)(seq0 + s) * TSZ + tp + j] = sY[j*16 + s];
        }
    }
}

extern "C" void kernel_launch(void* const* d_in, const int* in_sizes, int n_in,
                              void* d_out, int out_size) {
    (void)in_sizes; (void)n_in; (void)out_size;
    const float* in    = (const float*)d_in[0];
    const float* W_ih1 = (const float*)d_in[1];
    const float* W_hh1 = (const float*)d_in[2];
    const float* b_ih1 = (const float*)d_in[3];
    const float* b_hh1 = (const float*)d_in[4];
    const float* W_ih2 = (const float*)d_in[5];
    const float* W_hh2 = (const float*)d_in[6];
    const float* b_ih2 = (const float*)d_in[7];
    const float* b_hh2 = (const float*)d_in[8];
    const float* W_lin = (const float*)d_in[9];
    const float* b_lin = (const float*)d_in[10];
    float* out = (float*)d_out;

    const size_t smem = (size_t)SMEM_FLOATS * sizeof(float);   // ~168 KB
    cudaFuncSetAttribute(lstm2_kernel,
                         cudaFuncAttributeMaxDynamicSharedMemorySize, (int)smem);
    lstm2_kernel<<<NBLK, NT, smem>>>(in, W_ih1, W_hh1, b_ih1, b_hh1,
                                     W_ih2, W_hh2, b_ih2, b_hh2,
                                     W_lin, b_lin, out);
}